// round 8
// baseline (speedup 1.0000x reference)
#include <cuda_runtime.h>
#include <math.h>
#include <stdint.h>

#define NMAX 100000
#define EMAX 1600000
#define DIM 64

__device__ float g_hW[(size_t)NMAX * DIM];
__device__ float g_acc[(size_t)NMAX * DIM];
__device__ float g_pool[64 * DIM];
__device__ int   g_is64;
__device__ int   g_deg[NMAX];
__device__ int   g_off[NMAX + 1];
__device__ int   g_cursor[NMAX];
__device__ int   g_bsum[1024];
__device__ int   g_srcs[EMAX];

// ---------------------------------------------------------------------------
__device__ __forceinline__ void split_tf32(float x, float& hi, float& lo) {
    uint32_t h;
    asm("cvt.rna.tf32.f32 %0, %1;" : "=r"(h) : "f"(x));
    float r = x - __uint_as_float(h);
    uint32_t l;
    asm("cvt.rna.tf32.f32 %0, %1;" : "=r"(l) : "f"(r));
    hi = __uint_as_float(h); lo = __uint_as_float(l);
}

__device__ __forceinline__ void mma_tf32(float* c, uint32_t a0, uint32_t a1,
                                         uint32_t a2, uint32_t a3,
                                         uint32_t b0, uint32_t b1) {
    asm volatile(
        "mma.sync.aligned.m16n8k8.row.col.f32.tf32.tf32.f32 "
        "{%0,%1,%2,%3}, {%4,%5,%6,%7}, {%8,%9}, {%0,%1,%2,%3};"
        : "+f"(c[0]), "+f"(c[1]), "+f"(c[2]), "+f"(c[3])
        : "r"(a0), "r"(a1), "r"(a2), "r"(a3), "r"(b0), "r"(b1));
}

// 3xTF32 from pre-split planes: C += Ahi*Bhi + Ahi*Blo + Alo*Bhi
__device__ __forceinline__ void mma3(float* c,
    const uint32_t* ah, const uint32_t* al,
    uint32_t bh0, uint32_t bh1, uint32_t bl0, uint32_t bl1) {
    mma_tf32(c, ah[0], ah[1], ah[2], ah[3], bh0, bh1);
    mma_tf32(c, ah[0], ah[1], ah[2], ah[3], bl0, bl1);
    mma_tf32(c, al[0], al[1], al[2], al[3], bh0, bh1);
}

#define LD4U(dst_h, dst_l, Ph, Pl, idx0, idx1, idx2, idx3) \
    dst_h[0] = __float_as_uint(Ph[idx0]); dst_l[0] = __float_as_uint(Pl[idx0]); \
    dst_h[1] = __float_as_uint(Ph[idx1]); dst_l[1] = __float_as_uint(Pl[idx1]); \
    dst_h[2] = __float_as_uint(Ph[idx2]); dst_l[2] = __float_as_uint(Pl[idx2]); \
    dst_h[3] = __float_as_uint(Ph[idx3]); dst_l[3] = __float_as_uint(Pl[idx3]);

// ---------------------------------------------------------------------------
// zero + dtype detect (int64 edge_index => every odd 32-bit word is 0)
__global__ void zero_kernel(const int* __restrict__ e, int M) {
    int t = blockIdx.x * blockDim.x + threadIdx.x;
    if (t == 0) {
        int all0 = 1;
        #pragma unroll
        for (int i = 1; i < 64; i += 2) all0 &= (e[i] == 0);
        g_is64 = all0;
    }
    if (t < 64 * DIM) g_pool[t] = 0.0f;
    for (int i = t; i < M; i += blockDim.x * gridDim.x) g_deg[i] = 0;
}

// ---------------------------------------------------------------------------
// CSR build
__global__ __launch_bounds__(256) void hist_kernel(const void* __restrict__ eidx, int E) {
    int e = blockIdx.x * 256 + threadIdx.x;
    if (e >= E) return;
    int dst;
    if (g_is64) dst = (int)__ldg(&((const long long*)eidx)[E + e]);
    else        dst = __ldg(&((const int*)eidx)[E + e]);
    atomicAdd(&g_deg[dst], 1);
}

// exclusive scan of degrees, 1024 per block; block totals -> g_bsum
__global__ __launch_bounds__(256) void scan_local_kernel(int M) {
    __shared__ int warp_tot[8];
    __shared__ int wbase[8];
    const int t = threadIdx.x;
    const int idx0 = blockIdx.x * 1024 + t * 4;
    int v[4];
    #pragma unroll
    for (int i = 0; i < 4; i++) v[i] = (idx0 + i < M) ? g_deg[idx0 + i] : 0;
    int tot = v[0] + v[1] + v[2] + v[3];
    const int lane = t & 31, w = t >> 5;
    int sc = tot;
    #pragma unroll
    for (int o = 1; o < 32; o <<= 1) {
        int n = __shfl_up_sync(0xffffffffu, sc, o);
        if (lane >= o) sc += n;
    }
    if (lane == 31) warp_tot[w] = sc;
    __syncthreads();
    if (t == 0) {
        int s = 0;
        #pragma unroll
        for (int i = 0; i < 8; i++) { wbase[i] = s; s += warp_tot[i]; }
        g_bsum[blockIdx.x] = s;
    }
    __syncthreads();
    int run = sc - tot + wbase[w];
    #pragma unroll
    for (int i = 0; i < 4; i++) {
        if (idx0 + i < M) g_off[idx0 + i] = run;
        run += v[i];
    }
}

// add prefix of block totals (computed inline: <=98 adds by thread 0)
__global__ __launch_bounds__(256) void scan_add_kernel(int M, int E) {
    __shared__ int base_s;
    const int t = threadIdx.x;
    if (t == 0) {
        int nb = blockIdx.x >> 2;           // 256-chunks never cross 1024-chunks
        int s = 0;
        for (int i = 0; i < nb; i++) s += g_bsum[i];
        base_s = s;
    }
    __syncthreads();
    int i = blockIdx.x * 256 + t;
    if (i < M) {
        int o = g_off[i] + base_s;
        g_off[i] = o;
        g_cursor[i] = o;
    } else if (i == M) {
        g_off[M] = E;
    }
}

__global__ __launch_bounds__(256) void reorder_kernel(const void* __restrict__ eidx, int E) {
    int e = blockIdx.x * 256 + threadIdx.x;
    if (e >= E) return;
    int src, dst;
    if (g_is64) {
        const long long* p = (const long long*)eidx;
        src = (int)__ldg(&p[e]); dst = (int)__ldg(&p[E + e]);
    } else {
        const int* p = (const int*)eidx;
        src = __ldg(&p[e]); dst = __ldg(&p[E + e]);
    }
    int pos = atomicAdd(&g_cursor[dst], 1);
    g_srcs[pos] = src;
}

// ---------------------------------------------------------------------------
// Gather: one warp per dst node; half-warp h, lane-group j owns float4 j.
// Unrolled by 4 for memory-level parallelism.
__global__ __launch_bounds__(256) void gather_kernel(int M) {
    const int warp = (blockIdx.x * 256 + threadIdx.x) >> 5;
    if (warp >= M) return;
    const int lane = threadIdx.x & 31;
    const int h = lane >> 4;
    const int j = lane & 15;

    const int beg = g_off[warp], end = g_off[warp + 1];
    float4 acc = make_float4(0.f, 0.f, 0.f, 0.f);
    int k = beg + h;
    for (; k + 6 < end; k += 8) {
        int s0 = __ldg(&g_srcs[k]);
        int s1 = __ldg(&g_srcs[k + 2]);
        int s2 = __ldg(&g_srcs[k + 4]);
        int s3 = __ldg(&g_srcs[k + 6]);
        float4 v0 = __ldg((const float4*)(g_hW + (size_t)s0 * DIM) + j);
        float4 v1 = __ldg((const float4*)(g_hW + (size_t)s1 * DIM) + j);
        float4 v2 = __ldg((const float4*)(g_hW + (size_t)s2 * DIM) + j);
        float4 v3 = __ldg((const float4*)(g_hW + (size_t)s3 * DIM) + j);
        acc.x += (v0.x + v1.x) + (v2.x + v3.x);
        acc.y += (v0.y + v1.y) + (v2.y + v3.y);
        acc.z += (v0.z + v1.z) + (v2.z + v3.z);
        acc.w += (v0.w + v1.w) + (v2.w + v3.w);
    }
    for (; k < end; k += 2) {
        int s0 = __ldg(&g_srcs[k]);
        float4 v0 = __ldg((const float4*)(g_hW + (size_t)s0 * DIM) + j);
        acc.x += v0.x; acc.y += v0.y; acc.z += v0.z; acc.w += v0.w;
    }
    acc.x += __shfl_down_sync(0xffffffffu, acc.x, 16);
    acc.y += __shfl_down_sync(0xffffffffu, acc.y, 16);
    acc.z += __shfl_down_sync(0xffffffffu, acc.z, 16);
    acc.w += __shfl_down_sync(0xffffffffu, acc.w, 16);
    if (h == 0) {
        float4 self = __ldg((const float4*)(g_hW + (size_t)warp * DIM) + j);
        acc.x += self.x; acc.y += self.y; acc.z += self.z; acc.w += self.w;
        *((float4*)(g_acc + (size_t)warp * DIM) + j) = acc;
    }
}

// ---------------------------------------------------------------------------
// Layer-0 first linear: hW = X[M,128] @ W[128,64], 3xTF32 with pre-split planes.
__global__ __launch_bounds__(256) void lin0_kernel(
    const float* __restrict__ X, const float* __restrict__ W, int M)
{
    extern __shared__ float sm[];
    float* Xh = sm;                  // 64 x 132
    float* Xl = Xh + 64 * 132;       // 64 x 132
    float* Wh = Xl + 64 * 132;       // 128 x 72
    float* Wl = Wh + 128 * 72;       // 128 x 72
    const int t = threadIdx.x;
    const int row0 = blockIdx.x * 64;

    for (int i = t; i < 128 * 64; i += 256) {
        int k = i >> 6, q = i & 63;
        float hi, lo; split_tf32(W[k * 64 + q], hi, lo);
        Wh[k * 72 + q] = hi; Wl[k * 72 + q] = lo;
    }
    for (int i = t; i < 64 * 128; i += 256) {
        int r = i >> 7, kk = i & 127;
        int gr = row0 + r; if (gr >= M) gr = M - 1;
        float hi, lo; split_tf32(X[(size_t)gr * 128 + kk], hi, lo);
        Xh[r * 132 + kk] = hi; Xl[r * 132 + kk] = lo;
    }
    __syncthreads();

    const int w = t >> 5, lane = t & 31;
    const int gid = lane >> 2, tig = lane & 3;
    const int rows0 = (w >> 1) * 16;
    const int cols0 = (w & 1) * 32;

    float c[4][4] = {};
    #pragma unroll
    for (int k0 = 0; k0 < 16; k0++) {
        const int k = k0 * 8;
        uint32_t ah[4], al[4];
        int i0 = (rows0 + gid) * 132 + k + tig;
        int i1 = (rows0 + gid + 8) * 132 + k + tig;
        LD4U(ah, al, Xh, Xl, i0, i1, i0 + 4, i1 + 4);
        #pragma unroll
        for (int nf = 0; nf < 4; nf++) {
            int n = cols0 + nf * 8 + gid;
            int b0i = (k + tig) * 72 + n, b1i = b0i + 4 * 72;
            mma3(c[nf], ah, al,
                 __float_as_uint(Wh[b0i]), __float_as_uint(Wh[b1i]),
                 __float_as_uint(Wl[b0i]), __float_as_uint(Wl[b1i]));
        }
    }
    #pragma unroll
    for (int nf = 0; nf < 4; nf++) {
        int n = cols0 + nf * 8 + 2 * tig;
        int r0 = row0 + rows0 + gid, r1 = r0 + 8;
        if (r0 < M) {
            g_hW[(size_t)r0 * DIM + n]     = c[nf][0];
            g_hW[(size_t)r0 * DIM + n + 1] = c[nf][1];
        }
        if (r1 < M) {
            g_hW[(size_t)r1 * DIM + n]     = c[nf][2];
            g_hW[(size_t)r1 * DIM + n + 1] = c[nf][3];
        }
    }
}

// ---------------------------------------------------------------------------
// Node MLP on 3xTF32 with pre-split smem planes.
template <bool NEXT>
__global__ __launch_bounds__(256) void node_kernel(
    const float* __restrict__ ba, const float* __restrict__ gam,
    const float* __restrict__ bet, const float* __restrict__ Wb,
    const float* __restrict__ bb, const float* __restrict__ Wn,
    const void* __restrict__ batchp, int M)
{
    extern __shared__ float sm[];
    float* zh  = sm;                 // 64 x 68
    float* zl  = zh + 64 * 68;       // 64 x 68
    float* Wbh = zl + 64 * 68;       // 64 x 72
    float* Wbl = Wbh + 64 * 72;      // 64 x 72
    float* Wnh = Wbl + 64 * 72;      // 64 x 72 (NEXT only)
    float* Wnl = Wnh + 64 * 72;      // 64 x 72 (NEXT only)
    __shared__ float A[64], B[64], bbs[64];
    __shared__ int sbat[64];

    const int t = threadIdx.x;
    const int row0 = blockIdx.x * 64;

    if (t < 64) {
        float inv = rsqrtf(1.0f + 1e-5f);
        float a = gam[t] * inv;
        A[t] = a;
        B[t] = ba[t] * a + bet[t];
        bbs[t] = bb[t];
    }
    for (int i = t; i < 64 * 64; i += 256) {
        int k = i >> 6, q = i & 63;
        float hi, lo; split_tf32(Wb[i], hi, lo);
        Wbh[k * 72 + q] = hi; Wbl[k * 72 + q] = lo;
        if (NEXT) {
            split_tf32(Wn[i], hi, lo);
            Wnh[k * 72 + q] = hi; Wnl[k * 72 + q] = lo;
        }
    }
    __syncthreads();   // A/B ready

    // load acc tile, affine+relu, split -> zh/zl
    for (int i = t; i < 64 * 64; i += 256) {
        int r = i >> 6, cc = i & 63;
        int gr = row0 + r; if (gr >= M) gr = M - 1;
        float v = g_acc[(size_t)gr * DIM + cc];
        v = fmaxf(v * A[cc] + B[cc], 0.0f);
        float hi, lo; split_tf32(v, hi, lo);
        zh[r * 68 + cc] = hi; zl[r * 68 + cc] = lo;
    }
    __syncthreads();

    const int w = t >> 5, lane = t & 31;
    const int gid = lane >> 2, tig = lane & 3;
    const int rows0 = (w >> 1) * 16;
    const int cols0 = (w & 1) * 32;

    // ---- GEMM1: h = relu(z @ Wb + bb) ----
    float c1[4][4] = {};
    #pragma unroll
    for (int k0 = 0; k0 < 8; k0++) {
        const int k = k0 * 8;
        uint32_t ah[4], al[4];
        int i0 = (rows0 + gid) * 68 + k + tig;
        int i1 = (rows0 + gid + 8) * 68 + k + tig;
        LD4U(ah, al, zh, zl, i0, i1, i0 + 4, i1 + 4);
        #pragma unroll
        for (int nf = 0; nf < 4; nf++) {
            int n = cols0 + nf * 8 + gid;
            int b0i = (k + tig) * 72 + n, b1i = b0i + 4 * 72;
            mma3(c1[nf], ah, al,
                 __float_as_uint(Wbh[b0i]), __float_as_uint(Wbh[b1i]),
                 __float_as_uint(Wbl[b0i]), __float_as_uint(Wbl[b1i]));
        }
    }
    __syncthreads();   // all reads of z done
    // epilogue: bias+relu; store split (NEXT) or plain h (pooling) into zh/zl
    #pragma unroll
    for (int nf = 0; nf < 4; nf++) {
        int n = cols0 + nf * 8 + 2 * tig;
        int r0 = rows0 + gid, r1 = r0 + 8;
        float h00 = fmaxf(c1[nf][0] + bbs[n],     0.0f);
        float h01 = fmaxf(c1[nf][1] + bbs[n + 1], 0.0f);
        float h10 = fmaxf(c1[nf][2] + bbs[n],     0.0f);
        float h11 = fmaxf(c1[nf][3] + bbs[n + 1], 0.0f);
        if (NEXT) {
            float hi, lo;
            split_tf32(h00, hi, lo); zh[r0 * 68 + n]     = hi; zl[r0 * 68 + n]     = lo;
            split_tf32(h01, hi, lo); zh[r0 * 68 + n + 1] = hi; zl[r0 * 68 + n + 1] = lo;
            split_tf32(h10, hi, lo); zh[r1 * 68 + n]     = hi; zl[r1 * 68 + n]     = lo;
            split_tf32(h11, hi, lo); zh[r1 * 68 + n + 1] = hi; zl[r1 * 68 + n + 1] = lo;
        } else {
            zh[r0 * 68 + n]     = h00; zh[r0 * 68 + n + 1] = h01;
            zh[r1 * 68 + n]     = h10; zh[r1 * 68 + n + 1] = h11;
        }
    }
    __syncthreads();   // h fully in smem

    if (NEXT) {
        // ---- GEMM2: hW' = h @ Wn -> g_hW ----
        float c2[4][4] = {};
        #pragma unroll
        for (int k0 = 0; k0 < 8; k0++) {
            const int k = k0 * 8;
            uint32_t ah[4], al[4];
            int i0 = (rows0 + gid) * 68 + k + tig;
            int i1 = (rows0 + gid + 8) * 68 + k + tig;
            LD4U(ah, al, zh, zl, i0, i1, i0 + 4, i1 + 4);
            #pragma unroll
            for (int nf = 0; nf < 4; nf++) {
                int n = cols0 + nf * 8 + gid;
                int b0i = (k + tig) * 72 + n, b1i = b0i + 4 * 72;
                mma3(c2[nf], ah, al,
                     __float_as_uint(Wnh[b0i]), __float_as_uint(Wnh[b1i]),
                     __float_as_uint(Wnl[b0i]), __float_as_uint(Wnl[b1i]));
            }
        }
        #pragma unroll
        for (int nf = 0; nf < 4; nf++) {
            int n = cols0 + nf * 8 + 2 * tig;
            int r0 = row0 + rows0 + gid, r1 = r0 + 8;
            if (r0 < M) {
                g_hW[(size_t)r0 * DIM + n]     = c2[nf][0];
                g_hW[(size_t)r0 * DIM + n + 1] = c2[nf][1];
            }
            if (r1 < M) {
                g_hW[(size_t)r1 * DIM + n]     = c2[nf][2];
                g_hW[(size_t)r1 * DIM + n + 1] = c2[nf][3];
            }
        }
    } else {
        // ---- pooling (batch sorted): run-length reduce per column ----
        if (t < 64) {
            int gr = row0 + t;
            int b = -1;
            if (gr < M) {
                if (g_is64) b = (int)((const long long*)batchp)[gr];
                else        b = ((const int*)batchp)[gr];
            }
            sbat[t] = b;
        }
        __syncthreads();
        if (t < 64) {
            const int c = t;
            float s = 0.0f;
            int cur = sbat[0];
            for (int r = 0; r < 64; r++) {
                int b = sbat[r];
                if (b < 0) break;
                if (b != cur) {
                    atomicAdd(&g_pool[cur * DIM + c], s);
                    s = 0.0f; cur = b;
                }
                s += zh[r * 68 + c];
            }
            if (cur >= 0) atomicAdd(&g_pool[cur * DIM + c], s);
        }
    }
}

// ---------------------------------------------------------------------------
__global__ __launch_bounds__(256) void cls_kernel(
    const float* __restrict__ Wl1, const float* __restrict__ bl1,
    const float* __restrict__ Wl2, const float* __restrict__ bl2,
    float* __restrict__ out)
{
    extern __shared__ float sm[];
    float* ps  = sm;             // 64 x 64 pooled
    float* Ws1 = ps + 4096;      // 64 x 64 summed Wl1
    float* z1  = Ws1 + 4096;     // 64 x 65
    const int t = threadIdx.x;

    for (int i = t; i < 4096; i += 256) {
        ps[i]  = g_pool[i];
        Ws1[i] = Wl1[i] + Wl1[4096 + i] + Wl1[8192 + i];
    }
    __syncthreads();

    const int c = t & 63;
    const int gbase = (t >> 6) * 16;
    for (int gg = 0; gg < 16; gg++) {
        int g = gbase + gg;
        float s = bl1[c];
        #pragma unroll 8
        for (int k = 0; k < 64; k++) s += ps[g * 64 + k] * Ws1[k * 64 + c];
        z1[g * 65 + c] = fmaxf(s, 0.0f);
    }
    __syncthreads();

    if (t < 64) {
        const int g = t;
        float a = bl2[0], b = bl2[1];
        #pragma unroll 8
        for (int k = 0; k < 64; k++) {
            float v = z1[g * 65 + k];
            a += v * Wl2[k * 2 + 0];
            b += v * Wl2[k * 2 + 1];
        }
        float m = fmaxf(a, b);
        float l = m + logf(expf(a - m) + expf(b - m));
        out[2 * g + 0] = a - l;
        out[2 * g + 1] = b - l;
    }
}

// ---------------------------------------------------------------------------
extern "C" void kernel_launch(void* const* d_in, const int* in_sizes, int n_in,
                              void* d_out, int out_size)
{
    const float* x     = (const float*)d_in[0];
    const void*  eidx  = d_in[1];
    const void*  batch = d_in[2];
    const float* W0a   = (const float*)d_in[3];
    const float* b0a   = (const float*)d_in[4];
    const float* g0    = (const float*)d_in[5];
    const float* be0   = (const float*)d_in[6];
    const float* W0b   = (const float*)d_in[7];
    const float* b0b   = (const float*)d_in[8];
    const float* Wsa   = (const float*)d_in[9];
    const float* bsa   = (const float*)d_in[10];
    const float* gs    = (const float*)d_in[11];
    const float* bes   = (const float*)d_in[12];
    const float* Wsb   = (const float*)d_in[13];
    const float* bsb   = (const float*)d_in[14];
    const float* Wl1   = (const float*)d_in[15];
    const float* bl1   = (const float*)d_in[16];
    const float* Wl2   = (const float*)d_in[17];
    const float* bl2   = (const float*)d_in[18];

    const int M = in_sizes[0] / 128;
    const int E = in_sizes[1] / 2;
    const int nblk = (M + 63) / 64;
    const int eblk = (E + 255) / 256;
    const int sblk = (M + 1023) / 1024;
    const int gblk = (M * 32 + 255) / 256;

    const size_t smem_lin0 = (64 * 132 * 2 + 128 * 72 * 2) * sizeof(float); // 141312
    const size_t smem_node = (64 * 68 * 2 + 64 * 72 * 4) * sizeof(float);   // 108544
    const size_t smem_cls  = (4096 + 4096 + 64 * 65) * sizeof(float);

    cudaFuncSetAttribute(lin0_kernel, cudaFuncAttributeMaxDynamicSharedMemorySize, (int)smem_lin0);
    cudaFuncSetAttribute(node_kernel<true>, cudaFuncAttributeMaxDynamicSharedMemorySize, (int)smem_node);
    cudaFuncSetAttribute(node_kernel<false>, cudaFuncAttributeMaxDynamicSharedMemorySize, (int)smem_node);
    cudaFuncSetAttribute(cls_kernel, cudaFuncAttributeMaxDynamicSharedMemorySize, (int)smem_cls);

    zero_kernel<<<64, 256>>>((const int*)eidx, M);

    // build dst-CSR once; reused by all 3 gathers
    hist_kernel<<<eblk, 256>>>(eidx, E);
    scan_local_kernel<<<sblk, 256>>>(M);
    scan_add_kernel<<<(M + 256) / 256 + 1, 256>>>(M, E);
    reorder_kernel<<<eblk, 256>>>(eidx, E);

    lin0_kernel<<<nblk, 256, smem_lin0>>>(x, W0a, M);
    gather_kernel<<<gblk, 256>>>(M);
    node_kernel<true><<<nblk, 256, smem_node>>>(b0a, g0, be0, W0b, b0b, Wsa, nullptr, M);
    gather_kernel<<<gblk, 256>>>(M);
    node_kernel<true><<<nblk, 256, smem_node>>>(bsa, gs, bes, Wsb, bsb, Wsa + 4096, nullptr, M);
    gather_kernel<<<gblk, 256>>>(M);
    node_kernel<false><<<nblk, 256, smem_node>>>(bsa + 64, gs + 64, bes + 64,
                                                 Wsb + 4096, bsb + 64, nullptr, batch, M);
    cls_kernel<<<1, 256, smem_cls>>>(Wl1, bl1, Wl2, bl2, (float*)d_out);
}

// round 9
// speedup vs baseline: 1.5577x; 1.5577x over previous
#include <cuda_runtime.h>
#include <math.h>
#include <stdint.h>

#define NMAX 100000
#define EMAX 1600000
#define DIM 64

__device__ float g_hW[(size_t)NMAX * DIM];
__device__ float g_acc[(size_t)NMAX * DIM];
__device__ float g_pool[64 * DIM];
__device__ int   g_is64;
__device__ int   g_deg[NMAX];
__device__ int   g_off[NMAX + 1];
__device__ int   g_cursor[NMAX];
__device__ int   g_bsum[1024];
__device__ int   g_srcs[EMAX];

// pre-split weight planes (hi/lo tf32): W0a | W0b | Wsb0 | Wsb1 | Wsa0 | Wsa1
#define OFF_W0A  0
#define OFF_W0B  8192
#define OFF_WSB0 12288
#define OFF_WSB1 16384
#define OFF_WSA0 20480
#define OFF_WSA1 24576
#define W_TOTAL  28672
__device__ float g_whi[W_TOTAL];
__device__ float g_wlo[W_TOTAL];

// ---------------------------------------------------------------------------
__device__ __forceinline__ float tf32r(float x) {
    uint32_t u;
    asm("cvt.rna.tf32.f32 %0, %1;" : "=r"(u) : "f"(x));
    return __uint_as_float(u);
}

__device__ __forceinline__ void split_tf32(float x, float& hi, float& lo) {
    float h = tf32r(x);
    hi = h;
    lo = tf32r(x - h);
}

__device__ __forceinline__ void mma_tf32(float* c, uint32_t a0, uint32_t a1,
                                         uint32_t a2, uint32_t a3,
                                         uint32_t b0, uint32_t b1) {
    asm volatile(
        "mma.sync.aligned.m16n8k8.row.col.f32.tf32.tf32.f32 "
        "{%0,%1,%2,%3}, {%4,%5,%6,%7}, {%8,%9}, {%0,%1,%2,%3};"
        : "+f"(c[0]), "+f"(c[1]), "+f"(c[2]), "+f"(c[3])
        : "r"(a0), "r"(a1), "r"(a2), "r"(a3), "r"(b0), "r"(b1));
}

// ---------------------------------------------------------------------------
// zero + dtype detect (int64 edge_index => every odd 32-bit word is 0)
__global__ void zero_kernel(const int* __restrict__ e, int M) {
    int t = blockIdx.x * blockDim.x + threadIdx.x;
    if (t == 0) {
        int all0 = 1;
        #pragma unroll
        for (int i = 1; i < 64; i += 2) all0 &= (e[i] == 0);
        g_is64 = all0;
    }
    if (t < 64 * DIM) g_pool[t] = 0.0f;
    for (int i = t; i < M; i += blockDim.x * gridDim.x) g_deg[i] = 0;
}

// split all weights into hi/lo planes once
__global__ __launch_bounds__(256) void split_weights_kernel(
    const float* __restrict__ W0a, const float* __restrict__ W0b,
    const float* __restrict__ Wsa, const float* __restrict__ Wsb)
{
    int i = blockIdx.x * 256 + threadIdx.x;
    if (i >= W_TOTAL) return;
    float v;
    if      (i < OFF_W0B)  v = W0a[i];
    else if (i < OFF_WSB0) v = W0b[i - OFF_W0B];
    else if (i < OFF_WSB1) v = Wsb[i - OFF_WSB0];
    else if (i < OFF_WSA0) v = Wsb[4096 + i - OFF_WSB1];
    else if (i < OFF_WSA1) v = Wsa[i - OFF_WSA0];
    else                   v = Wsa[4096 + i - OFF_WSA1];
    float hi, lo; split_tf32(v, hi, lo);
    g_whi[i] = hi; g_wlo[i] = lo;
}

// ---------------------------------------------------------------------------
// CSR build
__global__ __launch_bounds__(256) void hist_kernel(const void* __restrict__ eidx, int E) {
    int e = blockIdx.x * 256 + threadIdx.x;
    if (e >= E) return;
    int dst;
    if (g_is64) dst = (int)__ldg(&((const long long*)eidx)[E + e]);
    else        dst = __ldg(&((const int*)eidx)[E + e]);
    atomicAdd(&g_deg[dst], 1);
}

__global__ __launch_bounds__(256) void scan_local_kernel(int M) {
    __shared__ int warp_tot[8];
    __shared__ int wbase[8];
    const int t = threadIdx.x;
    const int idx0 = blockIdx.x * 1024 + t * 4;
    int v[4];
    #pragma unroll
    for (int i = 0; i < 4; i++) v[i] = (idx0 + i < M) ? g_deg[idx0 + i] : 0;
    int tot = v[0] + v[1] + v[2] + v[3];
    const int lane = t & 31, w = t >> 5;
    int sc = tot;
    #pragma unroll
    for (int o = 1; o < 32; o <<= 1) {
        int n = __shfl_up_sync(0xffffffffu, sc, o);
        if (lane >= o) sc += n;
    }
    if (lane == 31) warp_tot[w] = sc;
    __syncthreads();
    if (t == 0) {
        int s = 0;
        #pragma unroll
        for (int i = 0; i < 8; i++) { wbase[i] = s; s += warp_tot[i]; }
        g_bsum[blockIdx.x] = s;
    }
    __syncthreads();
    int run = sc - tot + wbase[w];
    #pragma unroll
    for (int i = 0; i < 4; i++) {
        if (idx0 + i < M) g_off[idx0 + i] = run;
        run += v[i];
    }
}

// add prefix of block totals (parallel reduce, not serial)
__global__ __launch_bounds__(256) void scan_add_kernel(int M, int E) {
    __shared__ int red[256];
    const int t = threadIdx.x;
    const int nb = blockIdx.x >> 2;        // 256-chunks never cross 1024-chunks
    int s = 0;
    for (int i = t; i < nb; i += 256) s += g_bsum[i];
    red[t] = s;
    __syncthreads();
    #pragma unroll
    for (int o = 128; o > 0; o >>= 1) {
        if (t < o) red[t] += red[t + o];
        __syncthreads();
    }
    const int base = red[0];
    int i = blockIdx.x * 256 + t;
    if (i < M) {
        int o = g_off[i] + base;
        g_off[i] = o;
        g_cursor[i] = o;
    } else if (i == M) {
        g_off[M] = E;
    }
}

__global__ __launch_bounds__(256) void reorder_kernel(const void* __restrict__ eidx, int E) {
    int e = blockIdx.x * 256 + threadIdx.x;
    if (e >= E) return;
    int src, dst;
    if (g_is64) {
        const long long* p = (const long long*)eidx;
        src = (int)__ldg(&p[e]); dst = (int)__ldg(&p[E + e]);
    } else {
        const int* p = (const int*)eidx;
        src = __ldg(&p[e]); dst = __ldg(&p[E + e]);
    }
    int pos = atomicAdd(&g_cursor[dst], 1);
    g_srcs[pos] = src;
}

// ---------------------------------------------------------------------------
// Gather: one warp per dst node; half-warp h, lane-group j owns float4 j.
__global__ __launch_bounds__(256) void gather_kernel(int M) {
    const int warp = (blockIdx.x * 256 + threadIdx.x) >> 5;
    if (warp >= M) return;
    const int lane = threadIdx.x & 31;
    const int h = lane >> 4;
    const int j = lane & 15;

    const int beg = g_off[warp], end = g_off[warp + 1];
    float4 acc = make_float4(0.f, 0.f, 0.f, 0.f);
    int k = beg + h;
    for (; k + 6 < end; k += 8) {
        int s0 = __ldg(&g_srcs[k]);
        int s1 = __ldg(&g_srcs[k + 2]);
        int s2 = __ldg(&g_srcs[k + 4]);
        int s3 = __ldg(&g_srcs[k + 6]);
        float4 v0 = __ldg((const float4*)(g_hW + (size_t)s0 * DIM) + j);
        float4 v1 = __ldg((const float4*)(g_hW + (size_t)s1 * DIM) + j);
        float4 v2 = __ldg((const float4*)(g_hW + (size_t)s2 * DIM) + j);
        float4 v3 = __ldg((const float4*)(g_hW + (size_t)s3 * DIM) + j);
        acc.x += (v0.x + v1.x) + (v2.x + v3.x);
        acc.y += (v0.y + v1.y) + (v2.y + v3.y);
        acc.z += (v0.z + v1.z) + (v2.z + v3.z);
        acc.w += (v0.w + v1.w) + (v2.w + v3.w);
    }
    for (; k < end; k += 2) {
        int s0 = __ldg(&g_srcs[k]);
        float4 v0 = __ldg((const float4*)(g_hW + (size_t)s0 * DIM) + j);
        acc.x += v0.x; acc.y += v0.y; acc.z += v0.z; acc.w += v0.w;
    }
    acc.x += __shfl_down_sync(0xffffffffu, acc.x, 16);
    acc.y += __shfl_down_sync(0xffffffffu, acc.y, 16);
    acc.z += __shfl_down_sync(0xffffffffu, acc.z, 16);
    acc.w += __shfl_down_sync(0xffffffffu, acc.w, 16);
    if (h == 0) {
        float4 self = __ldg((const float4*)(g_hW + (size_t)warp * DIM) + j);
        acc.x += self.x; acc.y += self.y; acc.z += self.z; acc.w += self.w;
        *((float4*)(g_acc + (size_t)warp * DIM) + j) = acc;
    }
}

// ---------------------------------------------------------------------------
// Layer-0 first linear: hW = X[M,128] @ W0a[128,64].
// 128 rows/block; A single-tf32, B = hi+lo planes (2 MMAs); K split into two
// 64-row weight stages sharing the same smem planes.
__global__ __launch_bounds__(256) void lin0_kernel(const float* __restrict__ X, int M)
{
    extern __shared__ float sm[];
    float* Xs = sm;                 // 128 x 132
    float* Wh = Xs + 128 * 132;     // 64 x 72
    float* Wl = Wh + 64 * 72;       // 64 x 72
    const int t = threadIdx.x;
    const int row0 = blockIdx.x * 128;

    // stage X (single tf32 round), vectorized
    for (int i = t; i < 128 * 32; i += 256) {
        int r = i >> 5, kk = i & 31;
        int gr = row0 + r; if (gr >= M) gr = M - 1;
        float4 v = *(const float4*)(X + (size_t)gr * 128 + kk * 4);
        v.x = tf32r(v.x); v.y = tf32r(v.y); v.z = tf32r(v.z); v.w = tf32r(v.w);
        *(float4*)(Xs + r * 132 + kk * 4) = v;
    }

    const int w = t >> 5, lane = t & 31;
    const int gid = lane >> 2, tig = lane & 3;
    const int rows0 = w * 16;           // warp-exclusive rows

    float c[2][4][4] = {};
    #pragma unroll
    for (int ks = 0; ks < 2; ks++) {
        __syncthreads();   // X staged / previous GEMM stage done
        for (int i = t; i < 64 * 16; i += 256) {
            int k = i >> 4, q = i & 15;
            *(float4*)(Wh + k * 72 + q * 4) =
                *(const float4*)(g_whi + OFF_W0A + (ks * 64 + k) * 64 + q * 4);
            *(float4*)(Wl + k * 72 + q * 4) =
                *(const float4*)(g_wlo + OFF_W0A + (ks * 64 + k) * 64 + q * 4);
        }
        __syncthreads();
        #pragma unroll
        for (int k0 = 0; k0 < 8; k0++) {
            const int kx = ks * 64 + k0 * 8;   // Xs column
            const int kw = k0 * 8;             // W smem row
            int i0 = (rows0 + gid) * 132 + kx + tig;
            int i1 = (rows0 + gid + 8) * 132 + kx + tig;
            uint32_t a0 = __float_as_uint(Xs[i0]);
            uint32_t a1 = __float_as_uint(Xs[i1]);
            uint32_t a2 = __float_as_uint(Xs[i0 + 4]);
            uint32_t a3 = __float_as_uint(Xs[i1 + 4]);
            #pragma unroll
            for (int half = 0; half < 2; half++) {
                #pragma unroll
                for (int nf = 0; nf < 4; nf++) {
                    int n = half * 32 + nf * 8 + gid;
                    int b0i = (kw + tig) * 72 + n, b1i = b0i + 288;
                    mma_tf32(c[half][nf], a0, a1, a2, a3,
                             __float_as_uint(Wh[b0i]), __float_as_uint(Wh[b1i]));
                    mma_tf32(c[half][nf], a0, a1, a2, a3,
                             __float_as_uint(Wl[b0i]), __float_as_uint(Wl[b1i]));
                }
            }
        }
    }
    #pragma unroll
    for (int half = 0; half < 2; half++)
        #pragma unroll
        for (int nf = 0; nf < 4; nf++) {
            int n = half * 32 + nf * 8 + 2 * tig;
            int r0 = row0 + rows0 + gid, r1 = r0 + 8;
            if (r0 < M) {
                g_hW[(size_t)r0 * DIM + n]     = c[half][nf][0];
                g_hW[(size_t)r0 * DIM + n + 1] = c[half][nf][1];
            }
            if (r1 < M) {
                g_hW[(size_t)r1 * DIM + n]     = c[half][nf][2];
                g_hW[(size_t)r1 * DIM + n + 1] = c[half][nf][3];
            }
        }
}

// ---------------------------------------------------------------------------
// Node MLP: affine+ReLU, GEMM1(+bias,ReLU), then GEMM2 (weights swapped into
// the same smem planes) or pooling. 128 rows/block, warp-exclusive rows.
template <bool NEXT>
__global__ __launch_bounds__(256) void node_kernel(
    const float* __restrict__ ba, const float* __restrict__ gam,
    const float* __restrict__ bet, int wb_off,
    const float* __restrict__ bb, int wn_off,
    const void* __restrict__ batchp, int M)
{
    extern __shared__ float sm[];
    float* zs = sm;                 // 128 x 68 (z, later h)
    float* Wh = zs + 128 * 68;      // 64 x 72
    float* Wl = Wh + 64 * 72;       // 64 x 72
    __shared__ float A[64], Bc[64], bbs[64];
    __shared__ int sbat[128];

    const int t = threadIdx.x;
    const int row0 = blockIdx.x * 128;

    if (t < 64) {
        float inv = rsqrtf(1.0f + 1e-5f);
        float a = gam[t] * inv;
        A[t] = a;
        Bc[t] = ba[t] * a + bet[t];
        bbs[t] = bb[t];
    }
    // stage Wb planes (pure float4 copies, no CVT)
    for (int i = t; i < 64 * 16; i += 256) {
        int k = i >> 4, q = i & 15;
        *(float4*)(Wh + k * 72 + q * 4) = *(const float4*)(g_whi + wb_off + k * 64 + q * 4);
        *(float4*)(Wl + k * 72 + q * 4) = *(const float4*)(g_wlo + wb_off + k * 64 + q * 4);
    }
    __syncthreads();   // A/Bc ready

    // stage z = tf32(relu(affine(acc))), vectorized
    for (int i = t; i < 128 * 16; i += 256) {
        int r = i >> 4, q = i & 15;
        int gr = row0 + r; if (gr >= M) gr = M - 1;
        float4 v = *(const float4*)(g_acc + (size_t)gr * DIM + q * 4);
        int cc = q * 4;
        v.x = tf32r(fmaxf(v.x * A[cc + 0] + Bc[cc + 0], 0.0f));
        v.y = tf32r(fmaxf(v.y * A[cc + 1] + Bc[cc + 1], 0.0f));
        v.z = tf32r(fmaxf(v.z * A[cc + 2] + Bc[cc + 2], 0.0f));
        v.w = tf32r(fmaxf(v.w * A[cc + 3] + Bc[cc + 3], 0.0f));
        *(float4*)(zs + r * 68 + cc) = v;
    }
    __syncthreads();

    const int w = t >> 5, lane = t & 31;
    const int gid = lane >> 2, tig = lane & 3;
    const int rows0 = w * 16;   // warp-exclusive rows

    // ---- GEMM1: h = relu(z @ Wb + bb) ----
    float c1[2][4][4] = {};
    #pragma unroll
    for (int k0 = 0; k0 < 8; k0++) {
        const int k = k0 * 8;
        int i0 = (rows0 + gid) * 68 + k + tig;
        int i1 = (rows0 + gid + 8) * 68 + k + tig;
        uint32_t a0 = __float_as_uint(zs[i0]);
        uint32_t a1 = __float_as_uint(zs[i1]);
        uint32_t a2 = __float_as_uint(zs[i0 + 4]);
        uint32_t a3 = __float_as_uint(zs[i1 + 4]);
        #pragma unroll
        for (int half = 0; half < 2; half++) {
            #pragma unroll
            for (int nf = 0; nf < 4; nf++) {
                int n = half * 32 + nf * 8 + gid;
                int b0i = (k + tig) * 72 + n, b1i = b0i + 288;
                mma_tf32(c1[half][nf], a0, a1, a2, a3,
                         __float_as_uint(Wh[b0i]), __float_as_uint(Wh[b1i]));
                mma_tf32(c1[half][nf], a0, a1, a2, a3,
                         __float_as_uint(Wl[b0i]), __float_as_uint(Wl[b1i]));
            }
        }
    }
    // epilogue into OWN rows (no barrier needed: this warp is the only z
    // reader/writer of rows rows0..rows0+15)
    #pragma unroll
    for (int half = 0; half < 2; half++)
        #pragma unroll
        for (int nf = 0; nf < 4; nf++) {
            int n = half * 32 + nf * 8 + 2 * tig;
            int r0 = rows0 + gid, r1 = r0 + 8;
            float h00 = fmaxf(c1[half][nf][0] + bbs[n],     0.0f);
            float h01 = fmaxf(c1[half][nf][1] + bbs[n + 1], 0.0f);
            float h10 = fmaxf(c1[half][nf][2] + bbs[n],     0.0f);
            float h11 = fmaxf(c1[half][nf][3] + bbs[n + 1], 0.0f);
            if (NEXT) { h00 = tf32r(h00); h01 = tf32r(h01); h10 = tf32r(h10); h11 = tf32r(h11); }
            zs[r0 * 68 + n]     = h00; zs[r0 * 68 + n + 1] = h01;
            zs[r1 * 68 + n]     = h10; zs[r1 * 68 + n + 1] = h11;
        }
    __syncthreads();   // all GEMM1 done; Wb planes free; h visible

    if (NEXT) {
        // swap in Wn planes
        for (int i = t; i < 64 * 16; i += 256) {
            int k = i >> 4, q = i & 15;
            *(float4*)(Wh + k * 72 + q * 4) = *(const float4*)(g_whi + wn_off + k * 64 + q * 4);
            *(float4*)(Wl + k * 72 + q * 4) = *(const float4*)(g_wlo + wn_off + k * 64 + q * 4);
        }
        __syncthreads();

        // ---- GEMM2: hW' = h @ Wn -> g_hW ----
        float c2[2][4][4] = {};
        #pragma unroll
        for (int k0 = 0; k0 < 8; k0++) {
            const int k = k0 * 8;
            int i0 = (rows0 + gid) * 68 + k + tig;
            int i1 = (rows0 + gid + 8) * 68 + k + tig;
            uint32_t a0 = __float_as_uint(zs[i0]);
            uint32_t a1 = __float_as_uint(zs[i1]);
            uint32_t a2 = __float_as_uint(zs[i0 + 4]);
            uint32_t a3 = __float_as_uint(zs[i1 + 4]);
            #pragma unroll
            for (int half = 0; half < 2; half++) {
                #pragma unroll
                for (int nf = 0; nf < 4; nf++) {
                    int n = half * 32 + nf * 8 + gid;
                    int b0i = (k + tig) * 72 + n, b1i = b0i + 288;
                    mma_tf32(c2[half][nf], a0, a1, a2, a3,
                             __float_as_uint(Wh[b0i]), __float_as_uint(Wh[b1i]));
                    mma_tf32(c2[half][nf], a0, a1, a2, a3,
                             __float_as_uint(Wl[b0i]), __float_as_uint(Wl[b1i]));
                }
            }
        }
        #pragma unroll
        for (int half = 0; half < 2; half++)
            #pragma unroll
            for (int nf = 0; nf < 4; nf++) {
                int n = half * 32 + nf * 8 + 2 * tig;
                int r0 = row0 + rows0 + gid, r1 = r0 + 8;
                if (r0 < M) {
                    g_hW[(size_t)r0 * DIM + n]     = c2[half][nf][0];
                    g_hW[(size_t)r0 * DIM + n + 1] = c2[half][nf][1];
                }
                if (r1 < M) {
                    g_hW[(size_t)r1 * DIM + n]     = c2[half][nf][2];
                    g_hW[(size_t)r1 * DIM + n + 1] = c2[half][nf][3];
                }
            }
    } else {
        // ---- pooling (batch sorted): run-length reduce per column ----
        for (int i = t; i < 128; i += 256) {
            int gr = row0 + i;
            int b = -1;
            if (gr < M) {
                if (g_is64) b = (int)((const long long*)batchp)[gr];
                else        b = ((const int*)batchp)[gr];
            }
            sbat[i] = b;
        }
        __syncthreads();
        if (t < 64) {
            const int c = t;
            float s = 0.0f;
            int cur = sbat[0];
            for (int r = 0; r < 128; r++) {
                int b = sbat[r];
                if (b < 0) break;
                if (b != cur) {
                    atomicAdd(&g_pool[cur * DIM + c], s);
                    s = 0.0f; cur = b;
                }
                s += zs[r * 68 + c];
            }
            if (cur >= 0) atomicAdd(&g_pool[cur * DIM + c], s);
        }
    }
}

// ---------------------------------------------------------------------------
__global__ __launch_bounds__(256) void cls_kernel(
    const float* __restrict__ Wl1, const float* __restrict__ bl1,
    const float* __restrict__ Wl2, const float* __restrict__ bl2,
    float* __restrict__ out)
{
    extern __shared__ float sm[];
    float* ps  = sm;             // 64 x 64 pooled
    float* Ws1 = ps + 4096;      // 64 x 64 summed Wl1
    float* z1  = Ws1 + 4096;     // 64 x 65
    const int t = threadIdx.x;

    for (int i = t; i < 4096; i += 256) {
        ps[i]  = g_pool[i];
        Ws1[i] = Wl1[i] + Wl1[4096 + i] + Wl1[8192 + i];
    }
    __syncthreads();

    const int c = t & 63;
    const int gbase = (t >> 6) * 16;
    for (int gg = 0; gg < 16; gg++) {
        int g = gbase + gg;
        float s = bl1[c];
        #pragma unroll 8
        for (int k = 0; k < 64; k++) s += ps[g * 64 + k] * Ws1[k * 64 + c];
        z1[g * 65 + c] = fmaxf(s, 0.0f);
    }
    __syncthreads();

    if (t < 64) {
        const int g = t;
        float a = bl2[0], b = bl2[1];
        #pragma unroll 8
        for (int k = 0; k < 64; k++) {
            float v = z1[g * 65 + k];
            a += v * Wl2[k * 2 + 0];
            b += v * Wl2[k * 2 + 1];
        }
        float m = fmaxf(a, b);
        float l = m + logf(expf(a - m) + expf(b - m));
        out[2 * g + 0] = a - l;
        out[2 * g + 1] = b - l;
    }
}

// ---------------------------------------------------------------------------
extern "C" void kernel_launch(void* const* d_in, const int* in_sizes, int n_in,
                              void* d_out, int out_size)
{
    const float* x     = (const float*)d_in[0];
    const void*  eidx  = d_in[1];
    const void*  batch = d_in[2];
    const float* W0a   = (const float*)d_in[3];
    const float* b0a   = (const float*)d_in[4];
    const float* g0    = (const float*)d_in[5];
    const float* be0   = (const float*)d_in[6];
    const float* W0b   = (const float*)d_in[7];
    const float* b0b   = (const float*)d_in[8];
    const float* Wsa   = (const float*)d_in[9];
    const float* bsa   = (const float*)d_in[10];
    const float* gs    = (const float*)d_in[11];
    const float* bes   = (const float*)d_in[12];
    const float* Wsb   = (const float*)d_in[13];
    const float* bsb   = (const float*)d_in[14];
    const float* Wl1   = (const float*)d_in[15];
    const float* bl1   = (const float*)d_in[16];
    const float* Wl2   = (const float*)d_in[17];
    const float* bl2   = (const float*)d_in[18];

    const int M = in_sizes[0] / 128;
    const int E = in_sizes[1] / 2;
    const int nblk = (M + 127) / 128;
    const int eblk = (E + 255) / 256;
    const int sblk = (M + 1023) / 1024;
    const int gblk = (M * 32 + 255) / 256;

    const size_t smem_lin0 = (128 * 132 + 64 * 72 * 2) * sizeof(float);  // 104448
    const size_t smem_node = (128 * 68 + 64 * 72 * 2) * sizeof(float);   // 71680
    const size_t smem_cls  = (4096 + 4096 + 64 * 65) * sizeof(float);

    cudaFuncSetAttribute(lin0_kernel, cudaFuncAttributeMaxDynamicSharedMemorySize, (int)smem_lin0);
    cudaFuncSetAttribute(node_kernel<true>, cudaFuncAttributeMaxDynamicSharedMemorySize, (int)smem_node);
    cudaFuncSetAttribute(node_kernel<false>, cudaFuncAttributeMaxDynamicSharedMemorySize, (int)smem_node);
    cudaFuncSetAttribute(cls_kernel, cudaFuncAttributeMaxDynamicSharedMemorySize, (int)smem_cls);

    zero_kernel<<<64, 256>>>((const int*)eidx, M);
    split_weights_kernel<<<(W_TOTAL + 255) / 256, 256>>>(W0a, W0b, Wsa, Wsb);

    // build dst-CSR once; reused by all 3 gathers
    hist_kernel<<<eblk, 256>>>(eidx, E);
    scan_local_kernel<<<sblk, 256>>>(M);
    scan_add_kernel<<<(M + 256) / 256 + 1, 256>>>(M, E);
    reorder_kernel<<<eblk, 256>>>(eidx, E);

    lin0_kernel<<<nblk, 256, smem_lin0>>>(x, M);
    gather_kernel<<<gblk, 256>>>(M);
    node_kernel<true><<<nblk, 256, smem_node>>>(b0a, g0, be0, OFF_W0B, b0b, OFF_WSA0, nullptr, M);
    gather_kernel<<<gblk, 256>>>(M);
    node_kernel<true><<<nblk, 256, smem_node>>>(bsa, gs, bes, OFF_WSB0, bsb, OFF_WSA1, nullptr, M);
    gather_kernel<<<gblk, 256>>>(M);
    node_kernel<false><<<nblk, 256, smem_node>>>(bsa + 64, gs + 64, bes + 64, OFF_WSB1,
                                                 bsb + 64, 0, batch, M);
    cls_kernel<<<1, 256, smem_cls>>>(Wl1, bl1, Wl2, bl2, (float*)d_out);
}

// round 10
// speedup vs baseline: 1.6483x; 1.0581x over previous
#include <cuda_runtime.h>
#include <cuda_bf16.h>
#include <math.h>
#include <stdint.h>

#define NMAX 100000
#define EMAX 1600000
#define DIM 64

// node features stored as bf16 (32 uints = 64 bf16 per row)
__device__ unsigned int g_hW[(size_t)NMAX * 32];
__device__ float g_acc[(size_t)NMAX * DIM];
__device__ float g_pool[64 * DIM];
__device__ int   g_is64;
__device__ int   g_deg[NMAX];
__device__ int   g_off[NMAX + 1];
__device__ int   g_cursor[NMAX];
__device__ int   g_bsum[1024];
__device__ int   g_srcs[EMAX];

// pre-split weight planes (hi/lo tf32): W0a | W0b | Wsb0 | Wsb1 | Wsa0 | Wsa1
#define OFF_W0A  0
#define OFF_W0B  8192
#define OFF_WSB0 12288
#define OFF_WSB1 16384
#define OFF_WSA0 20480
#define OFF_WSA1 24576
#define W_TOTAL  28672
__device__ float g_whi[W_TOTAL];
__device__ float g_wlo[W_TOTAL];

// ---------------------------------------------------------------------------
__device__ __forceinline__ float tf32r(float x) {
    uint32_t u;
    asm("cvt.rna.tf32.f32 %0, %1;" : "=r"(u) : "f"(x));
    return __uint_as_float(u);
}

__device__ __forceinline__ void split_tf32(float x, float& hi, float& lo) {
    float h = tf32r(x);
    hi = h;
    lo = tf32r(x - h);
}

__device__ __forceinline__ void mma_tf32(float* c, uint32_t a0, uint32_t a1,
                                         uint32_t a2, uint32_t a3,
                                         uint32_t b0, uint32_t b1) {
    asm volatile(
        "mma.sync.aligned.m16n8k8.row.col.f32.tf32.tf32.f32 "
        "{%0,%1,%2,%3}, {%4,%5,%6,%7}, {%8,%9}, {%0,%1,%2,%3};"
        : "+f"(c[0]), "+f"(c[1]), "+f"(c[2]), "+f"(c[3])
        : "r"(a0), "r"(a1), "r"(a2), "r"(a3), "r"(b0), "r"(b1));
}

__device__ __forceinline__ unsigned int pack_bf(float a, float b) {
    __nv_bfloat162 p = __floats2bfloat162_rn(a, b);
    return *(unsigned int*)&p;
}

__device__ __forceinline__ float4 unpack_bf4(uint2 u) {
    float2 f0 = __bfloat1622float2(*(__nv_bfloat162*)&u.x);
    float2 f1 = __bfloat1622float2(*(__nv_bfloat162*)&u.y);
    return make_float4(f0.x, f0.y, f1.x, f1.y);
}

// ---------------------------------------------------------------------------
// zero + dtype detect (int64 edge_index => every odd 32-bit word is 0)
__global__ void zero_kernel(const int* __restrict__ e, int M) {
    int t = blockIdx.x * blockDim.x + threadIdx.x;
    if (t == 0) {
        int all0 = 1;
        #pragma unroll
        for (int i = 1; i < 64; i += 2) all0 &= (e[i] == 0);
        g_is64 = all0;
    }
    if (t < 64 * DIM) g_pool[t] = 0.0f;
    for (int i = t; i < M; i += blockDim.x * gridDim.x) g_deg[i] = 0;
}

// split all weights into hi/lo tf32 planes once
__global__ __launch_bounds__(256) void split_weights_kernel(
    const float* __restrict__ W0a, const float* __restrict__ W0b,
    const float* __restrict__ Wsa, const float* __restrict__ Wsb)
{
    int i = blockIdx.x * 256 + threadIdx.x;
    if (i >= W_TOTAL) return;
    float v;
    if      (i < OFF_W0B)  v = W0a[i];
    else if (i < OFF_WSB0) v = W0b[i - OFF_W0B];
    else if (i < OFF_WSB1) v = Wsb[i - OFF_WSB0];
    else if (i < OFF_WSA0) v = Wsb[4096 + i - OFF_WSB1];
    else if (i < OFF_WSA1) v = Wsa[i - OFF_WSA0];
    else                   v = Wsa[4096 + i - OFF_WSA1];
    float hi, lo; split_tf32(v, hi, lo);
    g_whi[i] = hi; g_wlo[i] = lo;
}

// ---------------------------------------------------------------------------
// CSR build
__global__ __launch_bounds__(256) void hist_kernel(const void* __restrict__ eidx, int E) {
    int e = blockIdx.x * 256 + threadIdx.x;
    if (e >= E) return;
    int dst;
    if (g_is64) dst = (int)__ldg(&((const long long*)eidx)[E + e]);
    else        dst = __ldg(&((const int*)eidx)[E + e]);
    atomicAdd(&g_deg[dst], 1);
}

__global__ __launch_bounds__(256) void scan_local_kernel(int M) {
    __shared__ int warp_tot[8];
    __shared__ int wbase[8];
    const int t = threadIdx.x;
    const int idx0 = blockIdx.x * 1024 + t * 4;
    int v[4];
    #pragma unroll
    for (int i = 0; i < 4; i++) v[i] = (idx0 + i < M) ? g_deg[idx0 + i] : 0;
    int tot = v[0] + v[1] + v[2] + v[3];
    const int lane = t & 31, w = t >> 5;
    int sc = tot;
    #pragma unroll
    for (int o = 1; o < 32; o <<= 1) {
        int n = __shfl_up_sync(0xffffffffu, sc, o);
        if (lane >= o) sc += n;
    }
    if (lane == 31) warp_tot[w] = sc;
    __syncthreads();
    if (t == 0) {
        int s = 0;
        #pragma unroll
        for (int i = 0; i < 8; i++) { wbase[i] = s; s += warp_tot[i]; }
        g_bsum[blockIdx.x] = s;
    }
    __syncthreads();
    int run = sc - tot + wbase[w];
    #pragma unroll
    for (int i = 0; i < 4; i++) {
        if (idx0 + i < M) g_off[idx0 + i] = run;
        run += v[i];
    }
}

// add prefix of block totals (parallel reduce)
__global__ __launch_bounds__(256) void scan_add_kernel(int M, int E) {
    __shared__ int red[256];
    const int t = threadIdx.x;
    const int nb = blockIdx.x >> 2;        // 256-chunks never cross 1024-chunks
    int s = 0;
    for (int i = t; i < nb; i += 256) s += g_bsum[i];
    red[t] = s;
    __syncthreads();
    #pragma unroll
    for (int o = 128; o > 0; o >>= 1) {
        if (t < o) red[t] += red[t + o];
        __syncthreads();
    }
    const int base = red[0];
    int i = blockIdx.x * 256 + t;
    if (i < M) {
        int o = g_off[i] + base;
        g_off[i] = o;
        g_cursor[i] = o;
    } else if (i == M) {
        g_off[M] = E;
    }
}

__global__ __launch_bounds__(256) void reorder_kernel(const void* __restrict__ eidx, int E) {
    int e = blockIdx.x * 256 + threadIdx.x;
    if (e >= E) return;
    int src, dst;
    if (g_is64) {
        const long long* p = (const long long*)eidx;
        src = (int)__ldg(&p[e]); dst = (int)__ldg(&p[E + e]);
    } else {
        const int* p = (const int*)eidx;
        src = __ldg(&p[e]); dst = __ldg(&p[E + e]);
    }
    int pos = atomicAdd(&g_cursor[dst], 1);
    g_srcs[pos] = src;
}

// ---------------------------------------------------------------------------
// Gather: one warp per dst node; half-warp h, lane j owns uint2 j (4 bf16).
// Row = 128 B = one cache line; fp32 accumulation; g_acc written fp32.
__global__ __launch_bounds__(256) void gather_kernel(int M) {
    const int warp = (blockIdx.x * 256 + threadIdx.x) >> 5;
    if (warp >= M) return;
    const int lane = threadIdx.x & 31;
    const int h = lane >> 4;
    const int j = lane & 15;

    const uint2* hw = (const uint2*)g_hW;
    const int beg = g_off[warp], end = g_off[warp + 1];
    float4 acc = make_float4(0.f, 0.f, 0.f, 0.f);
    int k = beg + h;
    for (; k + 6 < end; k += 8) {
        int s0 = __ldg(&g_srcs[k]);
        int s1 = __ldg(&g_srcs[k + 2]);
        int s2 = __ldg(&g_srcs[k + 4]);
        int s3 = __ldg(&g_srcs[k + 6]);
        float4 v0 = unpack_bf4(__ldg(hw + (size_t)s0 * 16 + j));
        float4 v1 = unpack_bf4(__ldg(hw + (size_t)s1 * 16 + j));
        float4 v2 = unpack_bf4(__ldg(hw + (size_t)s2 * 16 + j));
        float4 v3 = unpack_bf4(__ldg(hw + (size_t)s3 * 16 + j));
        acc.x += (v0.x + v1.x) + (v2.x + v3.x);
        acc.y += (v0.y + v1.y) + (v2.y + v3.y);
        acc.z += (v0.z + v1.z) + (v2.z + v3.z);
        acc.w += (v0.w + v1.w) + (v2.w + v3.w);
    }
    for (; k < end; k += 2) {
        int s0 = __ldg(&g_srcs[k]);
        float4 v0 = unpack_bf4(__ldg(hw + (size_t)s0 * 16 + j));
        acc.x += v0.x; acc.y += v0.y; acc.z += v0.z; acc.w += v0.w;
    }
    acc.x += __shfl_down_sync(0xffffffffu, acc.x, 16);
    acc.y += __shfl_down_sync(0xffffffffu, acc.y, 16);
    acc.z += __shfl_down_sync(0xffffffffu, acc.z, 16);
    acc.w += __shfl_down_sync(0xffffffffu, acc.w, 16);
    if (h == 0) {
        float4 self = unpack_bf4(__ldg(hw + (size_t)warp * 16 + j));
        acc.x += self.x; acc.y += self.y; acc.z += self.z; acc.w += self.w;
        *((float4*)(g_acc + (size_t)warp * DIM) + j) = acc;
    }
}

// ---------------------------------------------------------------------------
// Layer-0 first linear: hW = X[M,128] @ W0a[128,64] -> bf16.
// 128 rows/block; A single-tf32, B = hi+lo planes (2 MMAs); K in two stages.
__global__ __launch_bounds__(256) void lin0_kernel(const float* __restrict__ X, int M)
{
    extern __shared__ float sm[];
    float* Xs = sm;                 // 128 x 132
    float* Wh = Xs + 128 * 132;     // 64 x 72
    float* Wl = Wh + 64 * 72;       // 64 x 72
    const int t = threadIdx.x;
    const int row0 = blockIdx.x * 128;

    for (int i = t; i < 128 * 32; i += 256) {
        int r = i >> 5, kk = i & 31;
        int gr = row0 + r; if (gr >= M) gr = M - 1;
        float4 v = *(const float4*)(X + (size_t)gr * 128 + kk * 4);
        v.x = tf32r(v.x); v.y = tf32r(v.y); v.z = tf32r(v.z); v.w = tf32r(v.w);
        *(float4*)(Xs + r * 132 + kk * 4) = v;
    }

    const int w = t >> 5, lane = t & 31;
    const int gid = lane >> 2, tig = lane & 3;
    const int rows0 = w * 16;           // warp-exclusive rows

    float c[2][4][4] = {};
    #pragma unroll
    for (int ks = 0; ks < 2; ks++) {
        __syncthreads();
        for (int i = t; i < 64 * 16; i += 256) {
            int k = i >> 4, q = i & 15;
            *(float4*)(Wh + k * 72 + q * 4) =
                *(const float4*)(g_whi + OFF_W0A + (ks * 64 + k) * 64 + q * 4);
            *(float4*)(Wl + k * 72 + q * 4) =
                *(const float4*)(g_wlo + OFF_W0A + (ks * 64 + k) * 64 + q * 4);
        }
        __syncthreads();
        #pragma unroll
        for (int k0 = 0; k0 < 8; k0++) {
            const int kx = ks * 64 + k0 * 8;
            const int kw = k0 * 8;
            int i0 = (rows0 + gid) * 132 + kx + tig;
            int i1 = (rows0 + gid + 8) * 132 + kx + tig;
            uint32_t a0 = __float_as_uint(Xs[i0]);
            uint32_t a1 = __float_as_uint(Xs[i1]);
            uint32_t a2 = __float_as_uint(Xs[i0 + 4]);
            uint32_t a3 = __float_as_uint(Xs[i1 + 4]);
            #pragma unroll
            for (int half = 0; half < 2; half++) {
                #pragma unroll
                for (int nf = 0; nf < 4; nf++) {
                    int n = half * 32 + nf * 8 + gid;
                    int b0i = (kw + tig) * 72 + n, b1i = b0i + 288;
                    mma_tf32(c[half][nf], a0, a1, a2, a3,
                             __float_as_uint(Wh[b0i]), __float_as_uint(Wh[b1i]));
                    mma_tf32(c[half][nf], a0, a1, a2, a3,
                             __float_as_uint(Wl[b0i]), __float_as_uint(Wl[b1i]));
                }
            }
        }
    }
    #pragma unroll
    for (int half = 0; half < 2; half++)
        #pragma unroll
        for (int nf = 0; nf < 4; nf++) {
            int n = half * 32 + nf * 8 + 2 * tig;
            int r0 = row0 + rows0 + gid, r1 = r0 + 8;
            if (r0 < M) g_hW[(size_t)r0 * 32 + (n >> 1)] = pack_bf(c[half][nf][0], c[half][nf][1]);
            if (r1 < M) g_hW[(size_t)r1 * 32 + (n >> 1)] = pack_bf(c[half][nf][2], c[half][nf][3]);
        }
}

// ---------------------------------------------------------------------------
// Node MLP: affine+ReLU, GEMM1(+bias,ReLU), then GEMM2 -> bf16 hW or pooling.
// 128 rows/block, warp-exclusive rows, weight planes swapped between GEMMs.
template <bool NEXT>
__global__ __launch_bounds__(256) void node_kernel(
    const float* __restrict__ ba, const float* __restrict__ gam,
    const float* __restrict__ bet, int wb_off,
    const float* __restrict__ bb, int wn_off,
    const void* __restrict__ batchp, int M)
{
    extern __shared__ float sm[];
    float* zs = sm;                 // 128 x 68 (z, later h)
    float* Wh = zs + 128 * 68;      // 64 x 72
    float* Wl = Wh + 64 * 72;       // 64 x 72
    __shared__ float A[64], Bc[64], bbs[64];
    __shared__ int sbat[128];

    const int t = threadIdx.x;
    const int row0 = blockIdx.x * 128;

    if (t < 64) {
        float inv = rsqrtf(1.0f + 1e-5f);
        float a = gam[t] * inv;
        A[t] = a;
        Bc[t] = ba[t] * a + bet[t];
        bbs[t] = bb[t];
    }
    for (int i = t; i < 64 * 16; i += 256) {
        int k = i >> 4, q = i & 15;
        *(float4*)(Wh + k * 72 + q * 4) = *(const float4*)(g_whi + wb_off + k * 64 + q * 4);
        *(float4*)(Wl + k * 72 + q * 4) = *(const float4*)(g_wlo + wb_off + k * 64 + q * 4);
    }
    __syncthreads();   // A/Bc ready

    for (int i = t; i < 128 * 16; i += 256) {
        int r = i >> 4, q = i & 15;
        int gr = row0 + r; if (gr >= M) gr = M - 1;
        float4 v = *(const float4*)(g_acc + (size_t)gr * DIM + q * 4);
        int cc = q * 4;
        v.x = tf32r(fmaxf(v.x * A[cc + 0] + Bc[cc + 0], 0.0f));
        v.y = tf32r(fmaxf(v.y * A[cc + 1] + Bc[cc + 1], 0.0f));
        v.z = tf32r(fmaxf(v.z * A[cc + 2] + Bc[cc + 2], 0.0f));
        v.w = tf32r(fmaxf(v.w * A[cc + 3] + Bc[cc + 3], 0.0f));
        *(float4*)(zs + r * 68 + cc) = v;
    }
    __syncthreads();

    const int w = t >> 5, lane = t & 31;
    const int gid = lane >> 2, tig = lane & 3;
    const int rows0 = w * 16;

    // ---- GEMM1: h = relu(z @ Wb + bb) ----
    float c1[2][4][4] = {};
    #pragma unroll
    for (int k0 = 0; k0 < 8; k0++) {
        const int k = k0 * 8;
        int i0 = (rows0 + gid) * 68 + k + tig;
        int i1 = (rows0 + gid + 8) * 68 + k + tig;
        uint32_t a0 = __float_as_uint(zs[i0]);
        uint32_t a1 = __float_as_uint(zs[i1]);
        uint32_t a2 = __float_as_uint(zs[i0 + 4]);
        uint32_t a3 = __float_as_uint(zs[i1 + 4]);
        #pragma unroll
        for (int half = 0; half < 2; half++) {
            #pragma unroll
            for (int nf = 0; nf < 4; nf++) {
                int n = half * 32 + nf * 8 + gid;
                int b0i = (k + tig) * 72 + n, b1i = b0i + 288;
                mma_tf32(c1[half][nf], a0, a1, a2, a3,
                         __float_as_uint(Wh[b0i]), __float_as_uint(Wh[b1i]));
                mma_tf32(c1[half][nf], a0, a1, a2, a3,
                         __float_as_uint(Wl[b0i]), __float_as_uint(Wl[b1i]));
            }
        }
    }
    // epilogue into OWN rows (warp-exclusive, no barrier needed)
    #pragma unroll
    for (int half = 0; half < 2; half++)
        #pragma unroll
        for (int nf = 0; nf < 4; nf++) {
            int n = half * 32 + nf * 8 + 2 * tig;
            int r0 = rows0 + gid, r1 = r0 + 8;
            float h00 = fmaxf(c1[half][nf][0] + bbs[n],     0.0f);
            float h01 = fmaxf(c1[half][nf][1] + bbs[n + 1], 0.0f);
            float h10 = fmaxf(c1[half][nf][2] + bbs[n],     0.0f);
            float h11 = fmaxf(c1[half][nf][3] + bbs[n + 1], 0.0f);
            if (NEXT) { h00 = tf32r(h00); h01 = tf32r(h01); h10 = tf32r(h10); h11 = tf32r(h11); }
            zs[r0 * 68 + n]     = h00; zs[r0 * 68 + n + 1] = h01;
            zs[r1 * 68 + n]     = h10; zs[r1 * 68 + n + 1] = h11;
        }
    __syncthreads();   // GEMM1 done; Wb planes free; h visible

    if (NEXT) {
        for (int i = t; i < 64 * 16; i += 256) {
            int k = i >> 4, q = i & 15;
            *(float4*)(Wh + k * 72 + q * 4) = *(const float4*)(g_whi + wn_off + k * 64 + q * 4);
            *(float4*)(Wl + k * 72 + q * 4) = *(const float4*)(g_wlo + wn_off + k * 64 + q * 4);
        }
        __syncthreads();

        // ---- GEMM2: hW' = h @ Wn -> g_hW (bf16) ----
        float c2[2][4][4] = {};
        #pragma unroll
        for (int k0 = 0; k0 < 8; k0++) {
            const int k = k0 * 8;
            int i0 = (rows0 + gid) * 68 + k + tig;
            int i1 = (rows0 + gid + 8) * 68 + k + tig;
            uint32_t a0 = __float_as_uint(zs[i0]);
            uint32_t a1 = __float_as_uint(zs[i1]);
            uint32_t a2 = __float_as_uint(zs[i0 + 4]);
            uint32_t a3 = __float_as_uint(zs[i1 + 4]);
            #pragma unroll
            for (int half = 0; half < 2; half++) {
                #pragma unroll
                for (int nf = 0; nf < 4; nf++) {
                    int n = half * 32 + nf * 8 + gid;
                    int b0i = (k + tig) * 72 + n, b1i = b0i + 288;
                    mma_tf32(c2[half][nf], a0, a1, a2, a3,
                             __float_as_uint(Wh[b0i]), __float_as_uint(Wh[b1i]));
                    mma_tf32(c2[half][nf], a0, a1, a2, a3,
                             __float_as_uint(Wl[b0i]), __float_as_uint(Wl[b1i]));
                }
            }
        }
        #pragma unroll
        for (int half = 0; half < 2; half++)
            #pragma unroll
            for (int nf = 0; nf < 4; nf++) {
                int n = half * 32 + nf * 8 + 2 * tig;
                int r0 = row0 + rows0 + gid, r1 = r0 + 8;
                if (r0 < M) g_hW[(size_t)r0 * 32 + (n >> 1)] = pack_bf(c2[half][nf][0], c2[half][nf][1]);
                if (r1 < M) g_hW[(size_t)r1 * 32 + (n >> 1)] = pack_bf(c2[half][nf][2], c2[half][nf][3]);
            }
    } else {
        // ---- pooling (batch sorted): run-length reduce per column ----
        for (int i = t; i < 128; i += 256) {
            int gr = row0 + i;
            int b = -1;
            if (gr < M) {
                if (g_is64) b = (int)((const long long*)batchp)[gr];
                else        b = ((const int*)batchp)[gr];
            }
            sbat[i] = b;
        }
        __syncthreads();
        if (t < 64) {
            const int c = t;
            float s = 0.0f;
            int cur = sbat[0];
            for (int r = 0; r < 128; r++) {
                int b = sbat[r];
                if (b < 0) break;
                if (b != cur) {
                    atomicAdd(&g_pool[cur * DIM + c], s);
                    s = 0.0f; cur = b;
                }
                s += zs[r * 68 + c];
            }
            if (cur >= 0) atomicAdd(&g_pool[cur * DIM + c], s);
        }
    }
}

// ---------------------------------------------------------------------------
__global__ __launch_bounds__(256) void cls_kernel(
    const float* __restrict__ Wl1, const float* __restrict__ bl1,
    const float* __restrict__ Wl2, const float* __restrict__ bl2,
    float* __restrict__ out)
{
    extern __shared__ float sm[];
    float* ps  = sm;             // 64 x 64 pooled
    float* Ws1 = ps + 4096;      // 64 x 64 summed Wl1
    float* z1  = Ws1 + 4096;     // 64 x 65
    const int t = threadIdx.x;

    for (int i = t; i < 4096; i += 256) {
        ps[i]  = g_pool[i];
        Ws1[i] = Wl1[i] + Wl1[4096 + i] + Wl1[8192 + i];
    }
    __syncthreads();

    const int c = t & 63;
    const int gbase = (t >> 6) * 16;
    for (int gg = 0; gg < 16; gg++) {
        int g = gbase + gg;
        float s = bl1[c];
        #pragma unroll 8
        for (int k = 0; k < 64; k++) s += ps[g * 64 + k] * Ws1[k * 64 + c];
        z1[g * 65 + c] = fmaxf(s, 0.0f);
    }
    __syncthreads();

    if (t < 64) {
        const int g = t;
        float a = bl2[0], b = bl2[1];
        #pragma unroll 8
        for (int k = 0; k < 64; k++) {
            float v = z1[g * 65 + k];
            a += v * Wl2[k * 2 + 0];
            b += v * Wl2[k * 2 + 1];
        }
        float m = fmaxf(a, b);
        float l = m + logf(expf(a - m) + expf(b - m));
        out[2 * g + 0] = a - l;
        out[2 * g + 1] = b - l;
    }
}

// ---------------------------------------------------------------------------
extern "C" void kernel_launch(void* const* d_in, const int* in_sizes, int n_in,
                              void* d_out, int out_size)
{
    const float* x     = (const float*)d_in[0];
    const void*  eidx  = d_in[1];
    const void*  batch = d_in[2];
    const float* W0a   = (const float*)d_in[3];
    const float* b0a   = (const float*)d_in[4];
    const float* g0    = (const float*)d_in[5];
    const float* be0   = (const float*)d_in[6];
    const float* W0b   = (const float*)d_in[7];
    const float* b0b   = (const float*)d_in[8];
    const float* Wsa   = (const float*)d_in[9];
    const float* bsa   = (const float*)d_in[10];
    const float* gs    = (const float*)d_in[11];
    const float* bes   = (const float*)d_in[12];
    const float* Wsb   = (const float*)d_in[13];
    const float* bsb   = (const float*)d_in[14];
    const float* Wl1   = (const float*)d_in[15];
    const float* bl1   = (const float*)d_in[16];
    const float* Wl2   = (const float*)d_in[17];
    const float* bl2   = (const float*)d_in[18];

    const int M = in_sizes[0] / 128;
    const int E = in_sizes[1] / 2;
    const int nblk = (M + 127) / 128;
    const int eblk = (E + 255) / 256;
    const int sblk = (M + 1023) / 1024;
    const int gblk = (M * 32 + 255) / 256;

    const size_t smem_lin0 = (128 * 132 + 64 * 72 * 2) * sizeof(float);  // 104448
    const size_t smem_node = (128 * 68 + 64 * 72 * 2) * sizeof(float);   // 71680
    const size_t smem_cls  = (4096 + 4096 + 64 * 65) * sizeof(float);

    cudaFuncSetAttribute(lin0_kernel, cudaFuncAttributeMaxDynamicSharedMemorySize, (int)smem_lin0);
    cudaFuncSetAttribute(node_kernel<true>, cudaFuncAttributeMaxDynamicSharedMemorySize, (int)smem_node);
    cudaFuncSetAttribute(node_kernel<false>, cudaFuncAttributeMaxDynamicSharedMemorySize, (int)smem_node);
    cudaFuncSetAttribute(cls_kernel, cudaFuncAttributeMaxDynamicSharedMemorySize, (int)smem_cls);

    zero_kernel<<<64, 256>>>((const int*)eidx, M);
    split_weights_kernel<<<(W_TOTAL + 255) / 256, 256>>>(W0a, W0b, Wsa, Wsb);

    // build dst-CSR once; reused by all 3 gathers
    hist_kernel<<<eblk, 256>>>(eidx, E);
    scan_local_kernel<<<sblk, 256>>>(M);
    scan_add_kernel<<<(M + 256) / 256 + 1, 256>>>(M, E);
    reorder_kernel<<<eblk, 256>>>(eidx, E);

    lin0_kernel<<<nblk, 256, smem_lin0>>>(x, M);
    gather_kernel<<<gblk, 256>>>(M);
    node_kernel<true><<<nblk, 256, smem_node>>>(b0a, g0, be0, OFF_W0B, b0b, OFF_WSA0, nullptr, M);
    gather_kernel<<<gblk, 256>>>(M);
    node_kernel<true><<<nblk, 256, smem_node>>>(bsa, gs, bes, OFF_WSB0, bsb, OFF_WSA1, nullptr, M);
    gather_kernel<<<gblk, 256>>>(M);
    node_kernel<false><<<nblk, 256, smem_node>>>(bsa + 64, gs + 64, bes + 64, OFF_WSB1,
                                                 bsb + 64, 0, batch, M);
    cls_kernel<<<1, 256, smem_cls>>>(Wl1, bl1, Wl2, bl2, (float*)d_out);
}